// round 6
// baseline (speedup 1.0000x reference)
#include <cuda_runtime.h>

// CBOW negative-sampling loss, round 6: single fused kernel.
// ctx [B,CTX] i32, pos [B] i32, neg [B,NEG] i32, inW [V,D] f32, outW [V,D] f32 -> scalar f32.
#define VOCAB 50000
#define DIM   50
#define BATCH 131072
#define CTX   10
#define NEG   10

#define THREADS  256
#define WPB      (THREADS / 32)          // 8 samples per block
#define NBLOCKS  (BATCH / WPB)           // 16384
#define PER_T    (NBLOCKS / THREADS)     // 64 partials per finalizer thread

#define RSTRIDE  28                      // 28 floats = 112B rows (16B aligned)

__device__ __align__(16) float g_part[NBLOCKS];  // per-block loss partials
__device__ unsigned            g_cnt = 0;        // completion counter (self-resetting)

__global__ __launch_bounds__(THREADS, 4)
void cbow_fused(const int* __restrict__ ctx,
                const int* __restrict__ pos,
                const int* __restrict__ neg,
                const float* __restrict__ inW,
                const float* __restrict__ outW,
                float* __restrict__ out)
{
    __shared__ int s_ctx[WPB * CTX];
    __shared__ int s_neg[WPB * NEG];
    __shared__ int s_pos[WPB];
    __shared__ __align__(16) float s_red[WPB][11 * RSTRIDE];
    __shared__ float s_wl[WPB];
    __shared__ bool  s_last;

    const int tid  = threadIdx.x;
    const int lane = tid & 31;
    const int warp = tid >> 5;
    const int B0   = blockIdx.x * WPB;
    const unsigned FULL = 0xffffffffu;

    // ---- stage this block's 168 indices, coalesced ----
    if (tid < WPB * CTX) s_ctx[tid] = __ldg(&ctx[B0 * CTX + tid]);
    if (tid < WPB * NEG) s_neg[tid] = __ldg(&neg[B0 * NEG + tid]);
    if (tid < WPB)       s_pos[tid] = __ldg(&pos[B0 + tid]);
    __syncthreads();

    const float2* __restrict__ inW2  = (const float2*)inW;
    const float2* __restrict__ outW2 = (const float2*)outW;
    const bool act = (lane < 25);            // 25 lanes x float2 = 50 dims

    // ---- phase 1: CTX gathers (10 in flight) -> context mean ----
    float2 ce[CTX];
    #pragma unroll
    for (int c = 0; c < CTX; c++) {
        int r = s_ctx[warp * CTX + c];
        ce[c] = act ? __ldg(&inW2[r * 25 + lane]) : make_float2(0.f, 0.f);
    }
    float2 cv = make_float2(0.f, 0.f);
    #pragma unroll
    for (int c = 0; c < CTX; c++) { cv.x += ce[c].x; cv.y += ce[c].y; }
    cv.x *= (1.0f / CTX);
    cv.y *= (1.0f / CTX);

    // ---- phase 2: 11 out_embed gathers (11 in flight) ----
    float2 oe[NEG + 1];
    {
        int r = s_pos[warp];
        oe[0] = act ? __ldg(&outW2[r * 25 + lane]) : make_float2(0.f, 0.f);
    }
    #pragma unroll
    for (int k = 0; k < NEG; k++) {
        int r = s_neg[warp * NEG + k];
        oe[k + 1] = act ? __ldg(&outW2[r * 25 + lane]) : make_float2(0.f, 0.f);
    }

    // ---- per-lane partial dots ----
    float p[NEG + 1];
    #pragma unroll
    for (int j = 0; j <= NEG; j++)
        p[j] = cv.x * oe[j].x + cv.y * oe[j].y;

    // ---- smem transpose: lane j owns dot j ----
    if (act) {
        #pragma unroll
        for (int j = 0; j <= NEG; j++)
            s_red[warp][j * RSTRIDE + lane] = p[j];
    }
    __syncwarp();

    float term = 0.f;
    if (lane <= NEG) {
        const float* row = &s_red[warp][lane * RSTRIDE];
        float4 a = *(const float4*)(row);
        float4 b = *(const float4*)(row + 4);
        float4 c = *(const float4*)(row + 8);
        float4 d = *(const float4*)(row + 12);
        float4 e = *(const float4*)(row + 16);
        float4 f = *(const float4*)(row + 20);
        float s = ((a.x + a.y) + (a.z + a.w)) + ((b.x + b.y) + (b.z + b.w))
                + ((c.x + c.y) + (c.z + c.w)) + ((d.x + d.y) + (d.z + d.w))
                + ((e.x + e.y) + (e.z + e.w)) + ((f.x + f.y) + (f.z + f.w))
                + row[24];
        float arg = (lane == 0) ? s : -s;    // pos: +score, negs: -score
        float sg  = 1.0f / (1.0f + __expf(-arg));
        term = __logf(sg + 1e-10f);
    }
    #pragma unroll
    for (int o = 8; o > 0; o >>= 1)          // sum lanes 0..15 (11..15 zero)
        term += __shfl_xor_sync(FULL, term, o);

    if (lane == 0) s_wl[warp] = term;
    __syncthreads();

    // ---- per-block partial + completion count ----
    if (tid == 0) {
        float t = 0.f;
        #pragma unroll
        for (int i = 0; i < WPB; i++) t += s_wl[i];
        g_part[blockIdx.x] = t;
        __threadfence();
        unsigned old = atomicAdd(&g_cnt, 1u);
        s_last = (old == NBLOCKS - 1);
    }
    __syncthreads();
    if (!s_last) return;

    // ---- last block: deterministic fixed-order final sum of 16384 partials ----
    {
        const float4* __restrict__ p4 = (const float4*)g_part;   // 4096 float4
        float t = 0.f;
        #pragma unroll
        for (int i = 0; i < PER_T / 4; i++) {                    // 16 float4/thread
            float4 v = __ldcg(&p4[tid + i * THREADS]);
            t += ((v.x + v.y) + (v.z + v.w));
        }
        #pragma unroll
        for (int o = 16; o > 0; o >>= 1)
            t += __shfl_xor_sync(FULL, t, o);

        __shared__ float s_fin[WPB];
        if (lane == 0) s_fin[warp] = t;
        __syncthreads();
        if (tid == 0) {
            float v = 0.f;
            #pragma unroll
            for (int i = 0; i < WPB; i++) v += s_fin[i];
            out[0] = -v / (float)BATCH;
            g_cnt = 0;                        // reset for next graph replay
        }
    }
}

extern "C" void kernel_launch(void* const* d_in, const int* in_sizes, int n_in,
                              void* d_out, int out_size)
{
    const int*   ctx  = (const int*)d_in[0];   // [B, CTX]
    const int*   pos  = (const int*)d_in[1];   // [B]
    const int*   neg  = (const int*)d_in[2];   // [B, NEG]
    const float* inW  = (const float*)d_in[3]; // [VOCAB, DIM]
    const float* outW = (const float*)d_in[4]; // [VOCAB, DIM]
    float* out = (float*)d_out;

    cbow_fused<<<NBLOCKS, THREADS>>>(ctx, pos, neg, inW, outW, out);
}

// round 8
// speedup vs baseline: 1.4018x; 1.4018x over previous
#include <cuda_runtime.h>

// CBOW negative-sampling loss, round 7: occupancy-focused main + 2-launch reduce.
// ctx [B,CTX] i32, pos [B] i32, neg [B,NEG] i32, inW [V,D] f32, outW [V,D] f32 -> scalar f32.
#define VOCAB 50000
#define DIM   50
#define BATCH 131072
#define CTX   10
#define NEG   10

#define THREADS  128
#define WPB      (THREADS / 32)          // 4 samples per block
#define NBLOCKS  (BATCH / WPB)           // 32768
#define RED_B    256
#define RED_T    512                     // 256*512 = 131072 exact

#define RSTRIDE  28                      // 28 floats = 112B rows (16B aligned)

__device__ __align__(16) float g_wl[BATCH];   // per-sample loss
__device__ __align__(16) float g_red[RED_B];  // reduce partials
__device__ unsigned            g_cnt = 0;     // last-block counter (self-resetting)

__global__ __launch_bounds__(THREADS, 12)    // cap ~42 regs -> 1536 thr/SM (75% occ)
void cbow_main(const int* __restrict__ ctx,
               const int* __restrict__ pos,
               const int* __restrict__ neg,
               const float* __restrict__ inW,
               const float* __restrict__ outW)
{
    __shared__ int s_ctx[WPB * CTX];
    __shared__ int s_neg[WPB * NEG];
    __shared__ int s_pos[WPB];
    __shared__ __align__(16) float s_red[WPB][11 * RSTRIDE];

    const int tid  = threadIdx.x;
    const int lane = tid & 31;
    const int warp = tid >> 5;
    const int B0   = blockIdx.x * WPB;
    const unsigned FULL = 0xffffffffu;

    // ---- stage this block's indices, coalesced ----
    if (tid < WPB * CTX) s_ctx[tid] = __ldg(&ctx[B0 * CTX + tid]);
    if (tid < WPB * NEG) s_neg[tid] = __ldg(&neg[B0 * NEG + tid]);
    if (tid < WPB)       s_pos[tid] = __ldg(&pos[B0 + tid]);
    __syncthreads();

    const float2* __restrict__ inW2  = (const float2*)inW;
    const float2* __restrict__ outW2 = (const float2*)outW;
    const bool act = (lane < 25);            // 25 lanes x float2 = 50 dims

    // ---- context mean: 2 groups of 5 loads, fold immediately (low live regs) ----
    float2 cv = make_float2(0.f, 0.f);
    #pragma unroll
    for (int g = 0; g < 2; g++) {
        float2 t[5];
        #pragma unroll
        for (int c = 0; c < 5; c++) {
            int r = s_ctx[warp * CTX + g * 5 + c];
            t[c] = act ? __ldg(&inW2[r * 25 + lane]) : make_float2(0.f, 0.f);
        }
        #pragma unroll
        for (int c = 0; c < 5; c++) { cv.x += t[c].x; cv.y += t[c].y; }
    }
    cv.x *= (1.0f / CTX);
    cv.y *= (1.0f / CTX);

    // ---- 11 out_embed dots: 3 groups (4/4/3), fold to p[] immediately ----
    float p[NEG + 1];
    {
        float2 t[4];
        {
            int r = s_pos[warp];
            t[0] = act ? __ldg(&outW2[r * 25 + lane]) : make_float2(0.f, 0.f);
        }
        #pragma unroll
        for (int k = 0; k < 3; k++) {
            int r = s_neg[warp * NEG + k];
            t[k + 1] = act ? __ldg(&outW2[r * 25 + lane]) : make_float2(0.f, 0.f);
        }
        #pragma unroll
        for (int j = 0; j < 4; j++) p[j] = cv.x * t[j].x + cv.y * t[j].y;
    }
    {
        float2 t[4];
        #pragma unroll
        for (int k = 0; k < 4; k++) {
            int r = s_neg[warp * NEG + 3 + k];
            t[k] = act ? __ldg(&outW2[r * 25 + lane]) : make_float2(0.f, 0.f);
        }
        #pragma unroll
        for (int j = 0; j < 4; j++) p[4 + j] = cv.x * t[j].x + cv.y * t[j].y;
    }
    {
        float2 t[3];
        #pragma unroll
        for (int k = 0; k < 3; k++) {
            int r = s_neg[warp * NEG + 7 + k];
            t[k] = act ? __ldg(&outW2[r * 25 + lane]) : make_float2(0.f, 0.f);
        }
        #pragma unroll
        for (int j = 0; j < 3; j++) p[8 + j] = cv.x * t[j].x + cv.y * t[j].y;
    }

    // ---- smem transpose: lane j owns dot j ----
    if (act) {
        #pragma unroll
        for (int j = 0; j <= NEG; j++)
            s_red[warp][j * RSTRIDE + lane] = p[j];
    }
    __syncwarp();

    float term = 0.f;
    if (lane <= NEG) {
        const float* row = &s_red[warp][lane * RSTRIDE];
        float4 a = *(const float4*)(row);
        float4 b = *(const float4*)(row + 4);
        float4 c = *(const float4*)(row + 8);
        float4 d = *(const float4*)(row + 12);
        float4 e = *(const float4*)(row + 16);
        float4 f = *(const float4*)(row + 20);
        float s = ((a.x + a.y) + (a.z + a.w)) + ((b.x + b.y) + (b.z + b.w))
                + ((c.x + c.y) + (c.z + c.w)) + ((d.x + d.y) + (d.z + d.w))
                + ((e.x + e.y) + (e.z + e.w)) + ((f.x + f.y) + (f.z + f.w))
                + row[24];
        float arg = (lane == 0) ? s : -s;    // pos: +score, negs: -score
        float sg  = 1.0f / (1.0f + __expf(-arg));
        term = __logf(sg + 1e-10f);
    }
    #pragma unroll
    for (int o = 8; o > 0; o >>= 1)          // sum lanes 0..15 (11..15 zero)
        term += __shfl_xor_sync(FULL, term, o);

    // warp-granular retirement: no trailing block sync
    if (lane == 0) g_wl[B0 + warp] = term;
}

__global__ __launch_bounds__(RED_T)
void cbow_reduce(float* __restrict__ out)
{
    __shared__ float s[RED_T / 32];
    __shared__ bool  isLast;
    const int tid  = threadIdx.x;
    const int lane = tid & 31;
    const int warp = tid >> 5;
    const unsigned FULL = 0xffffffffu;

    float t = g_wl[blockIdx.x * RED_T + tid];
    #pragma unroll
    for (int o = 16; o > 0; o >>= 1)
        t += __shfl_xor_sync(FULL, t, o);
    if (lane == 0) s[warp] = t;
    __syncthreads();
    if (tid < 32) {
        float v = (tid < RED_T / 32) ? s[tid] : 0.f;
        #pragma unroll
        for (int o = 16; o > 0; o >>= 1)
            v += __shfl_xor_sync(FULL, v, o);
        if (tid == 0) {
            g_red[blockIdx.x] = v;
            __threadfence();
            unsigned old = atomicAdd(&g_cnt, 1u);
            isLast = (old == RED_B - 1);
        }
    }
    __syncthreads();

    if (isLast && tid < 32) {                 // deterministic fixed-order final sum
        float v = 0.f;
        #pragma unroll
        for (int i = 0; i < RED_B / 32; i++)
            v += __ldcg(&g_red[tid + i * 32]);
        #pragma unroll
        for (int o = 16; o > 0; o >>= 1)
            v += __shfl_xor_sync(FULL, v, o);
        if (tid == 0) {
            out[0] = -v / (float)BATCH;
            g_cnt = 0;                        // reset for next graph replay
        }
    }
}

extern "C" void kernel_launch(void* const* d_in, const int* in_sizes, int n_in,
                              void* d_out, int out_size)
{
    const int*   ctx  = (const int*)d_in[0];   // [B, CTX]
    const int*   pos  = (const int*)d_in[1];   // [B]
    const int*   neg  = (const int*)d_in[2];   // [B, NEG]
    const float* inW  = (const float*)d_in[3]; // [VOCAB, DIM]
    const float* outW = (const float*)d_in[4]; // [VOCAB, DIM]
    float* out = (float*)d_out;

    cbow_main<<<NBLOCKS, THREADS>>>(ctx, pos, neg, inW, outW);
    cbow_reduce<<<RED_B, RED_T>>>(out);
}